// round 1
// baseline (speedup 1.0000x reference)
#include <cuda_runtime.h>
#include <cstdint>

// QueryConditionedRouter: fused router GEMM + softmax + top-2
//   vis_emb  : (128, 576, 1024) f32  -> M = 73728 rows, K = 1024
//   query_emb: (8, 1024) f32
//   W_gate   : (64, 2048) f32  (W_vis = [:, :1024], W_qry = [:, 1024:])
// Outputs (concatenated float32):
//   topk_scores (M,2) | topk_idx (M,2, cast to float) | gate_scores (M,64) | gate_logits (M,64)

#define MROWS 73728
#define KDIM  1024
#define NEXP  64
#define KC    32            // k-chunk per smem stage
#define SPAD  34            // padded smem row stride (floats): bank-conflict-free LDS.64
#define TILE_FLOATS (64 * SPAD)   // 2176 floats per (A or B) stage
#define NCHUNK (KDIM / KC)  // 32

// scratch for query logits (8 x 64) — device global, no allocation
__device__ float g_qlog[512];

__device__ __forceinline__ void fma2(unsigned long long &d, unsigned long long a, unsigned long long b) {
    // packed 2x fp32 FMA (Blackwell FFMA2): d.lo += a.lo*b.lo ; d.hi += a.hi*b.hi
    asm volatile("fma.rn.f32x2 %0, %1, %2, %0;" : "+l"(d) : "l"(a), "l"(b));
}

__device__ __forceinline__ void cp8(uint32_t smem, const float* gmem) {
    asm volatile("cp.async.ca.shared.global [%0], [%1], 8;" :: "r"(smem), "l"(gmem));
}

// ---------------------------------------------------------------------------
// Kernel 0: qry_logits[b][e] = sum_q query[b][q] * W_gate[e][1024+q]
// One warp per (b,e) dot product; 512 warps total.
// ---------------------------------------------------------------------------
__global__ void qcr_qry_kernel(const float* __restrict__ qry, const float* __restrict__ Wg) {
    int w = (blockIdx.x * blockDim.x + threadIdx.x) >> 5;   // 0..511
    int lane = threadIdx.x & 31;
    if (w >= 512) return;
    int b = w >> 6;          // 0..7
    int e = w & 63;          // 0..63
    const float* qp = qry + (size_t)b * KDIM;
    const float* wp = Wg + (size_t)e * 2048 + 1024;
    float acc = 0.f;
    #pragma unroll 8
    for (int i = lane; i < KDIM; i += 32) acc += qp[i] * wp[i];
    #pragma unroll
    for (int o = 16; o; o >>= 1) acc += __shfl_xor_sync(0xffffffffu, acc, o);
    if (lane == 0) g_qlog[w] = acc;   // w == b*64 + e
}

// ---------------------------------------------------------------------------
// Kernel 1: main fused GEMM (64 rows x 64 experts per block) + softmax + top-2
// 256 threads: tx = tid&15 -> experts {tx, tx+16, tx+32, tx+48}
//              ty = tid>>4 -> rows    {ty, ty+16, ty+32, ty+48}
// Accumulators are f32x2 pairs over (k even, k odd) — both LDS.64 operands are
// naturally adjacent in row-major smem: no packs, no transpose.
// ---------------------------------------------------------------------------
__global__ void __launch_bounds__(256) qcr_main_kernel(
    const float* __restrict__ vis,
    const float* __restrict__ Wg,
    float* __restrict__ out)
{
    __shared__ __align__(16) float pool[4 * TILE_FLOATS];   // [buf][A|B][64][SPAD]
    __shared__ float qrow[64];
    __shared__ float rmax[64];
    __shared__ float rinv[64];

    const int tid = threadIdx.x;
    const int tx = tid & 15;
    const int ty = tid >> 4;
    const int rowbase = blockIdx.x * 64;

    // query logits for this block's batch index (tile never straddles b: 9216 % 64 == 0)
    if (tid < 64) qrow[tid] = g_qlog[(rowbase / 9216) * 64 + tid];

    unsigned long long acc[4][4];
    #pragma unroll
    for (int i = 0; i < 4; i++)
        #pragma unroll
        for (int j = 0; j < 4; j++) acc[i][j] = 0ULL;

    const uint32_t poolBase = (uint32_t)__cvta_generic_to_shared(pool);
    const float* Agbase = vis + (size_t)rowbase * KDIM;

    // ---- double-buffered cp.async pipeline over 32 k-chunks ----
    #define PREFETCH(c)                                                          \
    do {                                                                         \
        int _buf = (c) & 1;                                                      \
        uint32_t _sA = poolBase + _buf * (2 * TILE_FLOATS * 4);                  \
        uint32_t _sB = _sA + TILE_FLOATS * 4;                                    \
        const float* _Ag = Agbase + (c) * KC;                                    \
        const float* _Bg = Wg + (c) * KC;                                        \
        _Pragma("unroll")                                                        \
        for (int _t = 0; _t < 4; _t++) {                                         \
            int _u = tid + _t * 256;                                             \
            int _row = _u >> 4;                                                  \
            int _seg = (_u & 15) * 2;                                            \
            cp8(_sA + (uint32_t)(_row * SPAD + _seg) * 4,                        \
                _Ag + (size_t)_row * KDIM + _seg);                               \
            cp8(_sB + (uint32_t)(_row * SPAD + _seg) * 4,                        \
                _Bg + (size_t)_row * 2048 + _seg);                               \
        }                                                                        \
        asm volatile("cp.async.commit_group;");                                  \
    } while (0)

    PREFETCH(0);
    #pragma unroll 1
    for (int c = 0; c < NCHUNK; c++) {
        if (c + 1 < NCHUNK) {
            PREFETCH(c + 1);
            asm volatile("cp.async.wait_group 1;");
        } else {
            asm volatile("cp.async.wait_group 0;");
        }
        __syncthreads();

        const float* Ab = pool + (c & 1) * (2 * TILE_FLOATS);
        const float* Bb = Ab + TILE_FLOATS;
        const float* aRow = Ab + ty * SPAD;
        const float* bRow = Bb + tx * SPAD;

        #pragma unroll
        for (int kk = 0; kk < KC / 2; kk++) {
            unsigned long long a[4], b[4];
            #pragma unroll
            for (int i = 0; i < 4; i++)
                a[i] = *reinterpret_cast<const unsigned long long*>(aRow + i * 16 * SPAD + 2 * kk);
            #pragma unroll
            for (int j = 0; j < 4; j++)
                b[j] = *reinterpret_cast<const unsigned long long*>(bRow + j * 16 * SPAD + 2 * kk);
            #pragma unroll
            for (int i = 0; i < 4; i++)
                #pragma unroll
                for (int j = 0; j < 4; j++)
                    fma2(acc[i][j], a[i], b[j]);
        }
        __syncthreads();
    }

    // ---- epilogue: logits -> smem (reuse pool), softmax stats, top-2, outputs ----
    float* Ls = pool;   // 64 x 65 (padded), 4160 floats < pool capacity
    #pragma unroll
    for (int i = 0; i < 4; i++)
        #pragma unroll
        for (int j = 0; j < 4; j++) {
            unsigned long long v = acc[i][j];
            float lo = __uint_as_float((unsigned)(v & 0xffffffffu));
            float hi = __uint_as_float((unsigned)(v >> 32));
            int e = tx + 16 * j;
            Ls[(ty + 16 * i) * 65 + e] = lo + hi + qrow[e];
        }
    __syncthreads();

    const size_t O_TI = 2 * (size_t)MROWS;
    const size_t O_SC = 4 * (size_t)MROWS;
    const size_t O_LG = O_SC + (size_t)MROWS * NEXP;

    if (tid < 64) {
        const float* Lr = Ls + tid * 65;
        float m1 = -1e30f, m2 = -1e30f;
        int i1 = 0, i2 = 0;
        #pragma unroll
        for (int e = 0; e < 64; e++) {
            float v = Lr[e];
            if (v > m1) { m2 = m1; i2 = i1; m1 = v; i1 = e; }
            else if (v > m2) { m2 = v; i2 = e; }
        }
        float s = 0.f;
        #pragma unroll
        for (int e = 0; e < 64; e++) s += __expf(Lr[e] - m1);
        float inv = 1.0f / s;
        rmax[tid] = m1;
        rinv[tid] = inv;
        size_t g = (size_t)(rowbase + tid);
        out[g * 2 + 0] = inv;                          // exp(m1-m1)/s
        out[g * 2 + 1] = __expf(m2 - m1) * inv;
        out[O_TI + g * 2 + 0] = (float)i1;
        out[O_TI + g * 2 + 1] = (float)i2;
    }
    __syncthreads();

    // coalesced write of gate_scores and gate_logits
    for (int u = tid; u < 64 * 64; u += 256) {
        int r = u >> 6, e = u & 63;
        float l = Ls[r * 65 + e];
        size_t g = (size_t)(rowbase + r) * 64 + e;
        out[O_LG + g] = l;
        out[O_SC + g] = __expf(l - rmax[r]) * rinv[r];
    }
}

// ---------------------------------------------------------------------------
extern "C" void kernel_launch(void* const* d_in, const int* in_sizes, int n_in,
                              void* d_out, int out_size)
{
    const float* vis = (const float*)d_in[0];   // (128,576,1024) f32
    const float* qry = (const float*)d_in[1];   // (8,1024) f32
    const float* Wg  = (const float*)d_in[2];   // (64,2048) f32
    float* out = (float*)d_out;

    qcr_qry_kernel<<<64, 256>>>(qry, Wg);
    qcr_main_kernel<<<MROWS / 64, 256>>>(vis, Wg, out);
}

// round 3
// speedup vs baseline: 2.1904x; 2.1904x over previous
#include <cuda_runtime.h>
#include <cuda_fp16.h>
#include <cstdint>

// QueryConditionedRouter via mma.sync (HMMA) fp16 2-term split, 3 passes.
//   vis_emb  : (128, 576, 1024) f32  -> M = 73728 rows, K = 1024
//   query_emb: (8, 1024) f32
//   W_gate   : (64, 2048) f32  (W_vis = [:, :1024], W_qry = [:, 1024:])
// Output (concat f32): topk_scores (M,2) | topk_idx (M,2) | gate_scores (M,64) | gate_logits (M,64)
//
// Precision: logits = (A*2^12)*(B*2^5) accumulated in f32 via
//   Ahi*Bhi + Ahi*Blo + Alo*Bhi  (fp16 hi/lo split, residuals kept normal by
//   the exponent pre-scales), then * 2^-17. Logit abs error ~1e-7 -> no top-k flips.

#define MROWS   73728
#define KDIM    1024
#define NEXP    64
#define NBLOCKS (MROWS / 128)   // 576
#define ASCALE  4096.0f         // 2^12
#define BSCALE  32.0f           // 2^5
#define OSCALE  7.62939453125e-06f  // 2^-17

__device__ float g_qlog[512];
// B fragments, fragment-major: entry e = ((chunk*8 + ntile)*32 + lane)
//   uint4 = { hi(k0,k1), hi(k8,k9), lo(k0,k1), lo(k8,k9) }  (fp16x2 packed)
__device__ uint4 g_bfrag[64 * 8 * 32];

// split f32 pair (already pre-scaled) into fp16x2 hi + lo
__device__ __forceinline__ void split_pair(float f0, float f1, uint32_t &h, uint32_t &l) {
    __half2 hh = __floats2half2_rn(f0, f1);          // x = f0 (low), y = f1 (high)
    float g0 = __low2float(hh), g1 = __high2float(hh);
    __half2 ll = __floats2half2_rn(f0 - g0, f1 - g1);
    h = *reinterpret_cast<uint32_t*>(&hh);
    l = *reinterpret_cast<uint32_t*>(&ll);
}

__device__ __forceinline__ void mma16816(float* c, const uint32_t* a, uint32_t b0, uint32_t b1) {
    asm volatile(
        "mma.sync.aligned.m16n8k16.row.col.f32.f16.f16.f32 "
        "{%0,%1,%2,%3}, {%4,%5,%6,%7}, {%8,%9}, {%0,%1,%2,%3};"
        : "+f"(c[0]), "+f"(c[1]), "+f"(c[2]), "+f"(c[3])
        : "r"(a[0]), "r"(a[1]), "r"(a[2]), "r"(a[3]), "r"(b0), "r"(b1));
}

// ---------------------------------------------------------------------------
// Prep kernel: (a) qry logits, one warp per (b,e); (b) B fragment conversion,
// one thread per fragment entry. 64 blocks x 256 threads.
// ---------------------------------------------------------------------------
__global__ void qcr_prep_kernel(const float* __restrict__ qry, const float* __restrict__ Wg) {
    const int tid = blockIdx.x * 256 + threadIdx.x;

    // ---- query logits ----
    {
        int w = tid >> 5;                 // 0..511
        int lane = tid & 31;
        const float* qp = qry + (size_t)(w >> 6) * KDIM;
        const float* wp = Wg + (size_t)(w & 63) * 2048 + 1024;
        float acc = 0.f;
        #pragma unroll 8
        for (int i = lane; i < KDIM; i += 32) acc += qp[i] * wp[i];
        #pragma unroll
        for (int o = 16; o; o >>= 1) acc += __shfl_xor_sync(0xffffffffu, acc, o);
        if (lane == 0) g_qlog[w] = acc;
    }

    // ---- B fragments (W_vis, scaled by 2^5, fp16 hi/lo split) ----
    {
        int lane = tid & 31;
        int t = (tid >> 5) & 7;           // n8 tile
        int c = tid >> 8;                 // k16 chunk, 0..63
        int n = t * 8 + (lane >> 2);
        int k0 = c * 16 + (lane & 3) * 2;
        const float* wr = Wg + (size_t)n * 2048 + k0;
        float w0 = wr[0] * BSCALE, w1 = wr[1] * BSCALE;
        float w8 = wr[8] * BSCALE, w9 = wr[9] * BSCALE;
        uint4 v;
        split_pair(w0, w1, v.x, v.z);
        split_pair(w8, w9, v.y, v.w);
        g_bfrag[tid] = v;
    }
}

// ---------------------------------------------------------------------------
// Main kernel: 576 blocks x 256 threads. Warp w computes rows
// [rowbase + 16w, +16) x all 64 experts via m16n8k16 HMMA, A streamed from
// gmem f32 and split in registers, B fragments from g_bfrag (L1/L2 resident).
// ---------------------------------------------------------------------------
__global__ void __launch_bounds__(256, 2) qcr_main_kernel(
    const float* __restrict__ vis,
    float* __restrict__ out)
{
    __shared__ float Ls[128 * 65];
    __shared__ float qrow[64];

    const int tid = threadIdx.x;
    const int warp = tid >> 5;
    const int lane = tid & 31;
    const int grp = lane >> 2;        // 0..7
    const int tig = lane & 3;         // 0..3
    const int rowbase = blockIdx.x * 128;

    if (tid < 64) qrow[tid] = g_qlog[(rowbase / 9216) * 64 + tid];

    const int r0 = rowbase + warp * 16 + grp;
    const float2* A0 = reinterpret_cast<const float2*>(vis + (size_t)r0 * KDIM) + tig;
    const float2* A1 = reinterpret_cast<const float2*>(vis + (size_t)(r0 + 8) * KDIM) + tig;
    const uint4* Bf = g_bfrag + lane;

    float acc[8][4];
    #pragma unroll
    for (int t = 0; t < 8; t++)
        #pragma unroll
        for (int j = 0; j < 4; j++) acc[t][j] = 0.f;

    #pragma unroll 2
    for (int c = 0; c < 64; c++) {
        // A fragment: rows (r0, r0+8) x k pairs (k0,k0+1) and (k0+8,k0+9)
        float2 p00 = A0[c * 8];         // (r0,   k01)
        float2 p10 = A1[c * 8];         // (r0+8, k01)
        float2 p01 = A0[c * 8 + 4];     // (r0,   k89)
        float2 p11 = A1[c * 8 + 4];     // (r0+8, k89)

        uint32_t ah[4], al[4];
        split_pair(p00.x * ASCALE, p00.y * ASCALE, ah[0], al[0]);
        split_pair(p10.x * ASCALE, p10.y * ASCALE, ah[1], al[1]);
        split_pair(p01.x * ASCALE, p01.y * ASCALE, ah[2], al[2]);
        split_pair(p11.x * ASCALE, p11.y * ASCALE, ah[3], al[3]);

        #pragma unroll
        for (int t = 0; t < 8; t++) {
            uint4 b = Bf[(c * 8 + t) * 32];
            mma16816(acc[t], ah, b.x, b.y);   // Ahi * Bhi
            mma16816(acc[t], ah, b.z, b.w);   // Ahi * Blo
            mma16816(acc[t], al, b.x, b.y);   // Alo * Bhi
        }
    }

    // ---- stage logits to smem (rescale + add query logits) ----
    {
        const int rl0 = warp * 16 + grp;
        #pragma unroll
        for (int t = 0; t < 8; t++) {
            int col = t * 8 + tig * 2;
            float q0 = qrow[col], q1 = qrow[col + 1];
            Ls[rl0 * 65 + col]           = acc[t][0] * OSCALE + q0;
            Ls[rl0 * 65 + col + 1]       = acc[t][1] * OSCALE + q1;
            Ls[(rl0 + 8) * 65 + col]     = acc[t][2] * OSCALE + q0;
            Ls[(rl0 + 8) * 65 + col + 1] = acc[t][3] * OSCALE + q1;
        }
    }
    __syncthreads();

    // ---- per-row softmax + top-2 + outputs ----
    const size_t O_TI = 2 * (size_t)MROWS;
    const size_t O_SC = 4 * (size_t)MROWS;
    const size_t O_LG = O_SC + (size_t)MROWS * NEXP;

    if (tid < 128) {
        float d[64];
        const float* Lr = Ls + tid * 65;
        #pragma unroll
        for (int e = 0; e < 64; e++) d[e] = Lr[e];

        float m1 = -1e30f, m2 = -1e30f;
        int i1 = 0, i2 = 0;
        #pragma unroll
        for (int e = 0; e < 64; e++) {
            float v = d[e];
            if (v > m1) { m2 = m1; i2 = i1; m1 = v; i1 = e; }
            else if (v > m2) { m2 = v; i2 = e; }
        }
        float ssum = 0.f;
        #pragma unroll
        for (int e = 0; e < 64; e++) ssum += __expf(d[e] - m1);
        float inv = 1.0f / ssum;

        size_t g = (size_t)(rowbase + tid);
        out[g * 2 + 0] = inv;
        out[g * 2 + 1] = __expf(m2 - m1) * inv;
        out[O_TI + g * 2 + 0] = (float)i1;
        out[O_TI + g * 2 + 1] = (float)i2;

        float4* sc = reinterpret_cast<float4*>(out + O_SC + g * 64);
        float4* lg = reinterpret_cast<float4*>(out + O_LG + g * 64);
        #pragma unroll
        for (int e4 = 0; e4 < 16; e4++) {
            float4 lv = make_float4(d[e4 * 4], d[e4 * 4 + 1], d[e4 * 4 + 2], d[e4 * 4 + 3]);
            lg[e4] = lv;
            sc[e4] = make_float4(__expf(lv.x - m1) * inv, __expf(lv.y - m1) * inv,
                                 __expf(lv.z - m1) * inv, __expf(lv.w - m1) * inv);
        }
    }
}

// ---------------------------------------------------------------------------
extern "C" void kernel_launch(void* const* d_in, const int* in_sizes, int n_in,
                              void* d_out, int out_size)
{
    const float* vis = (const float*)d_in[0];
    const float* qry = (const float*)d_in[1];
    const float* Wg  = (const float*)d_in[2];
    float* out = (float*)d_out;

    qcr_prep_kernel<<<64, 256>>>(qry, Wg);
    qcr_main_kernel<<<NBLOCKS, 256>>>(vis, out);
}